// round 11
// baseline (speedup 1.0000x reference)
#include <cuda_runtime.h>
#include <cuda_bf16.h>
#include <cuda_fp16.h>
#include <math.h>
#include <stdint.h>

#define BB 16
#define LL 1024
#define DD 1024
#define HH 8
#define KHD 128
#define OUTN 64

typedef __nv_bfloat16  bf16;
typedef __nv_bfloat162 bf162;
typedef __half  h16;
typedef __half2 h162;

// ---------------- scratch ----------------
__device__ bf16 g_x1h[BB*LL*DD], g_x1l[BB*LL*DD];
__device__ bf16 g_x2h[BB*LL*DD], g_x2l[BB*LL*DD];
__device__ bf16 g_wkh[DD*DD], g_wkl[DD*DD];
__device__ bf16 g_wqh[DD*DD], g_wql[DD*DD];
__device__ bf16 g_qh[BB*LL*DD], g_ql[BB*LL*DD];
__device__ bf16 g_kh[BB*LL*DD], g_kl[BB*LL*DD];
__device__ h16 g_x0h[BB*LL*DD];
__device__ h16 g_wvh[DD*DD];
__device__ h16 g_wuh[DD*DD];
__device__ h16 g_vv [BB*LL*DD];
__device__ h16 g_att[BB*LL*DD];
__device__ float    g_psum[BB*DD];
__device__ unsigned g_pmax[BB*DD];

// ---------------- helpers ----------------
__device__ __forceinline__ void bsplit(float x, bf16& h, bf16& l) {
    h = __float2bfloat16_rn(x);
    l = __float2bfloat16_rn(x - __bfloat162float(h));
}
__device__ __forceinline__ uint32_t pkb(bf16 x, bf16 y) {
    bf162 t; t.x = x; t.y = y; return *(uint32_t*)&t;
}
__device__ __forceinline__ uint32_t pkh(h16 x, h16 y) {
    h162 t; t.x = x; t.y = y; return *(uint32_t*)&t;
}
__device__ __forceinline__ void cpa16(void* s, const void* g) {
    uint32_t sa = (uint32_t)__cvta_generic_to_shared(s);
    asm volatile("cp.async.cg.shared.global [%0], [%1], 16;" :: "r"(sa), "l"(g));
}
__device__ __forceinline__ void cp_commit() {
    asm volatile("cp.async.commit_group;" ::: "memory");
}
__device__ __forceinline__ void cp_wait1() {
    asm volatile("cp.async.wait_group 1;" ::: "memory");
}
__device__ __forceinline__ void cp_wait2() {
    asm volatile("cp.async.wait_group 2;" ::: "memory");
}
__device__ __forceinline__ void ldsm_x4(uint32_t* r, const void* p) {
    uint32_t a = (uint32_t)__cvta_generic_to_shared(p);
    asm volatile("ldmatrix.sync.aligned.m8n8.x4.shared.b16 {%0,%1,%2,%3}, [%4];"
        : "=r"(r[0]), "=r"(r[1]), "=r"(r[2]), "=r"(r[3]) : "r"(a));
}
__device__ __forceinline__ void ldsm_x4t(uint32_t* r, const void* p) {
    uint32_t a = (uint32_t)__cvta_generic_to_shared(p);
    asm volatile("ldmatrix.sync.aligned.m8n8.x4.trans.shared.b16 {%0,%1,%2,%3}, [%4];"
        : "=r"(r[0]), "=r"(r[1]), "=r"(r[2]), "=r"(r[3]) : "r"(a));
}
__device__ __forceinline__ void mma_bf16(float* c, const uint32_t* a, const uint32_t* b) {
    asm volatile(
        "mma.sync.aligned.m16n8k16.row.col.f32.bf16.bf16.f32 "
        "{%0,%1,%2,%3},{%4,%5,%6,%7},{%8,%9},{%0,%1,%2,%3};"
        : "+f"(c[0]), "+f"(c[1]), "+f"(c[2]), "+f"(c[3])
        : "r"(a[0]), "r"(a[1]), "r"(a[2]), "r"(a[3]), "r"(b[0]), "r"(b[1]));
}
__device__ __forceinline__ void mma_f16(float* c, const uint32_t* a, const uint32_t* b) {
    asm volatile(
        "mma.sync.aligned.m16n8k16.row.col.f32.f16.f16.f32 "
        "{%0,%1,%2,%3},{%4,%5,%6,%7},{%8,%9},{%0,%1,%2,%3};"
        : "+f"(c[0]), "+f"(c[1]), "+f"(c[2]), "+f"(c[3])
        : "r"(a[0]), "r"(a[1]), "r"(a[2]), "r"(a[3]), "r"(b[0]), "r"(b[1]));
}
__device__ __forceinline__ unsigned fkey(float v) {
    unsigned u = __float_as_uint(v);
    return (u & 0x80000000u) ? ~u : (u | 0x80000000u);
}
__device__ __forceinline__ float fdec(unsigned k) {
    unsigned u = (k & 0x80000000u) ? (k ^ 0x80000000u) : ~k;
    return __uint_as_float(u);
}

// =================================================================
// bf16 3-MMA TN GEMM, z-batched (q & k proj). BM=128, BN=256, BK=16,
// 4-stage cp.async, 8 warps, warp tile 64x64.
// =================================================================
__global__ void __launch_bounds__(256)
gemm_b3(const bf16* __restrict__ A0h, const bf16* __restrict__ A0l,
        const bf16* __restrict__ B0h, const bf16* __restrict__ B0l,
        bf16* __restrict__ C0h, bf16* __restrict__ C0l,
        const bf16* __restrict__ A1h, const bf16* __restrict__ A1l,
        const bf16* __restrict__ B1h, const bf16* __restrict__ B1l,
        bf16* __restrict__ C1h, bf16* __restrict__ C1l,
        float alpha)
{
    extern __shared__ __align__(16) char smem[];
    constexpr int RS   = 24;
    constexpr int ARRA = 128 * RS;      // A array elems
    constexpr int ARRB = 256 * RS;      // B array elems
    constexpr int STG  = 2 * ARRA + 2 * ARRB;   // 18432 elems

    const bf16* Ah = blockIdx.z ? A1h : A0h;
    const bf16* Al = blockIdx.z ? A1l : A0l;
    const bf16* Bh = blockIdx.z ? B1h : B0h;
    const bf16* Bl = blockIdx.z ? B1l : B0l;
    bf16* Ch = blockIdx.z ? C1h : C0h;
    bf16* Cl = blockIdx.z ? C1l : C0l;

    const int bm = blockIdx.y * 128, bn = blockIdx.x * 256;
    const int u = threadIdx.x, wid = u >> 5, lane = u & 31;
    const int wm = (wid >> 2) * 64, wn = (wid & 3) * 64;

    float acc[4][8][4];
    #pragma unroll
    for (int i = 0; i < 4; ++i)
        #pragma unroll
        for (int j = 0; j < 8; ++j)
            #pragma unroll
            for (int p = 0; p < 4; ++p) acc[i][j][p] = 0.f;

    const int srow = u >> 1, shalf = (u & 1) * 8;
    auto stage = [&](int buf, int k0) {
        bf16* s0 = (bf16*)smem + (long)buf * STG;
        const long ga = (long)(bm + srow) * DD + k0 + shalf;
        cpa16(s0 + srow * RS + shalf,        Ah + ga);
        cpa16(s0 + ARRA + srow * RS + shalf, Al + ga);
        bf16* sB = s0 + 2 * ARRA;
        #pragma unroll
        for (int r = 0; r < 2; ++r) {
            const int row = srow + r * 128;
            const long gb = (long)(bn + row) * DD + k0 + shalf;
            cpa16(sB + row * RS + shalf,        Bh + gb);
            cpa16(sB + ARRB + row * RS + shalf, Bl + gb);
        }
    };

    constexpr int nst = DD / 16;
    #pragma unroll
    for (int t = 0; t < 3; ++t) { stage(t, t * 16); cp_commit(); }

    const int arow = lane & 15, asel = (lane >> 4) * 8;
    const int brow = ((lane >> 4) & 1) * 8 + (lane & 7);
    const int bcol = ((lane >> 3) & 1) * 8;

    for (int s = 0; s < nst; ++s) {
        cp_wait2();
        __syncthreads();
        if (s + 3 < nst) stage((s + 3) & 3, (s + 3) * 16);
        cp_commit();

        const bf16* base = (const bf16*)smem + (long)(s & 3) * STG;
        const bf16* sAh = base;
        const bf16* sAl = base + ARRA;
        const bf16* sBh = base + 2 * ARRA;
        const bf16* sBl = base + 2 * ARRA + ARRB;

        uint32_t ah[4][4], al[4][4];
        #pragma unroll
        for (int mt = 0; mt < 4; ++mt) {
            const int off = (wm + mt * 16 + arow) * RS + asel;
            ldsm_x4(ah[mt], sAh + off);
            ldsm_x4(al[mt], sAl + off);
        }
        #pragma unroll
        for (int np = 0; np < 4; ++np) {
            uint32_t bh4[4], bl4[4];
            const int off = (wn + np * 16 + brow) * RS + bcol;
            ldsm_x4(bh4, sBh + off);
            ldsm_x4(bl4, sBl + off);
            #pragma unroll
            for (int half = 0; half < 2; ++half) {
                const int nt = np * 2 + half;
                #pragma unroll
                for (int mt = 0; mt < 4; ++mt) {
                    mma_bf16(acc[mt][nt], ah[mt], bh4 + half * 2);
                    mma_bf16(acc[mt][nt], ah[mt], bl4 + half * 2);
                    mma_bf16(acc[mt][nt], al[mt], bh4 + half * 2);
                }
            }
        }
    }

    const int tr = lane >> 2, tc = lane & 3;
    #pragma unroll
    for (int mt = 0; mt < 4; ++mt) {
        const int row = bm + wm + mt * 16 + tr;
        #pragma unroll
        for (int nt = 0; nt < 8; ++nt) {
            const int col = bn + wn + nt * 8 + tc * 2;
            const float* c = acc[mt][nt];
            bf16 h0, l0, h1, l1;
            bsplit(c[0] * alpha, h0, l0); bsplit(c[1] * alpha, h1, l1);
            *(uint32_t*)&Ch[(long)row * DD + col] = pkb(h0, h1);
            *(uint32_t*)&Cl[(long)row * DD + col] = pkb(l0, l1);
            bsplit(c[2] * alpha, h0, l0); bsplit(c[3] * alpha, h1, l1);
            *(uint32_t*)&Ch[(long)(row + 8) * DD + col] = pkb(h0, h1);
            *(uint32_t*)&Cl[(long)(row + 8) * DD + col] = pkb(l0, l1);
        }
    }
}

// =================================================================
// fp16 1-MMA TN GEMM. BM=128, BN=256, warp tile 64x64.
// POOL 0: fp16 C;  POOL 1: fused mean/max pool.
// =================================================================
template<int POOL>
__global__ void __launch_bounds__(256)
gemm_h1(const h16* __restrict__ Ax, const h16* __restrict__ Bh,
        h16* __restrict__ Chf, const float* __restrict__ bias,
        float* __restrict__ psum, unsigned* __restrict__ pmax)
{
    extern __shared__ __align__(16) char smem[];
    constexpr int RS   = 24;
    constexpr int ARRA = 128 * RS;
    constexpr int ARRB = 256 * RS;
    constexpr int STG  = ARRA + ARRB;

    const int bm = blockIdx.y * 128, bn = blockIdx.x * 256;
    const int u = threadIdx.x, wid = u >> 5, lane = u & 31;
    const int wm = (wid >> 2) * 64, wn = (wid & 3) * 64;

    float acc[4][8][4];
    #pragma unroll
    for (int i = 0; i < 4; ++i)
        #pragma unroll
        for (int j = 0; j < 8; ++j)
            #pragma unroll
            for (int p = 0; p < 4; ++p) acc[i][j][p] = 0.f;

    const int srow = u >> 1, shalf = (u & 1) * 8;
    auto stage = [&](int buf, int k0) {
        h16* s0 = (h16*)smem + (long)buf * STG;
        cpa16(s0 + srow * RS + shalf, Ax + (long)(bm + srow) * DD + k0 + shalf);
        h16* sB = s0 + ARRA;
        #pragma unroll
        for (int r = 0; r < 2; ++r) {
            const int row = srow + r * 128;
            cpa16(sB + row * RS + shalf, Bh + (long)(bn + row) * DD + k0 + shalf);
        }
    };

    constexpr int nst = DD / 16;
    #pragma unroll
    for (int t = 0; t < 3; ++t) { stage(t, t * 16); cp_commit(); }

    const int arow = lane & 15, asel = (lane >> 4) * 8;
    const int brow = ((lane >> 4) & 1) * 8 + (lane & 7);
    const int bcol = ((lane >> 3) & 1) * 8;

    for (int s = 0; s < nst; ++s) {
        cp_wait2();
        __syncthreads();
        if (s + 3 < nst) stage((s + 3) & 3, (s + 3) * 16);
        cp_commit();

        const h16* base = (const h16*)smem + (long)(s & 3) * STG;
        const h16* sA  = base;
        const h16* sBh = base + ARRA;

        uint32_t ah[4][4];
        #pragma unroll
        for (int mt = 0; mt < 4; ++mt)
            ldsm_x4(ah[mt], sA + (wm + mt * 16 + arow) * RS + asel);
        #pragma unroll
        for (int np = 0; np < 4; ++np) {
            uint32_t bh4[4];
            ldsm_x4(bh4, sBh + (wn + np * 16 + brow) * RS + bcol);
            #pragma unroll
            for (int half = 0; half < 2; ++half) {
                const int nt = np * 2 + half;
                #pragma unroll
                for (int mt = 0; mt < 4; ++mt)
                    mma_f16(acc[mt][nt], ah[mt], bh4 + half * 2);
            }
        }
    }

    const int tr = lane >> 2, tc = lane & 3;
    if (POOL == 0) {
        #pragma unroll
        for (int mt = 0; mt < 4; ++mt) {
            const int row = bm + wm + mt * 16 + tr;
            #pragma unroll
            for (int nt = 0; nt < 8; ++nt) {
                const int col = bn + wn + nt * 8 + tc * 2;
                const float* c = acc[mt][nt];
                *(uint32_t*)&Chf[(long)row * DD + col] =
                    pkh(__float2half_rn(c[0]), __float2half_rn(c[1]));
                *(uint32_t*)&Chf[(long)(row + 8) * DD + col] =
                    pkh(__float2half_rn(c[2]), __float2half_rn(c[3]));
            }
        }
    } else {
        const int b = bm >> 10;
        float sum[8][2], mx[8][2];
        #pragma unroll
        for (int nt = 0; nt < 8; ++nt) {
            #pragma unroll
            for (int j = 0; j < 2; ++j) {
                const int col = bn + wn + nt * 8 + tc * 2 + j;
                const float bv = __ldg(bias + col);
                float s_ = 0.f, m_ = -1e30f;
                #pragma unroll
                for (int mt = 0; mt < 4; ++mt) {
                    const float v0 = acc[mt][nt][j] + bv;
                    const float v1 = acc[mt][nt][j + 2] + bv;
                    s_ += v0 + v1;
                    m_ = fmaxf(m_, fmaxf(v0, v1));
                }
                sum[nt][j] = s_; mx[nt][j] = m_;
            }
        }
        #pragma unroll
        for (int o = 4; o <= 16; o <<= 1) {
            #pragma unroll
            for (int nt = 0; nt < 8; ++nt)
                #pragma unroll
                for (int j = 0; j < 2; ++j) {
                    sum[nt][j] += __shfl_xor_sync(~0u, sum[nt][j], o);
                    mx[nt][j] = fmaxf(mx[nt][j], __shfl_xor_sync(~0u, mx[nt][j], o));
                }
        }
        if (tr == 0) {
            #pragma unroll
            for (int nt = 0; nt < 8; ++nt)
                #pragma unroll
                for (int j = 0; j < 2; ++j) {
                    const int col = bn + wn + nt * 8 + tc * 2 + j;
                    atomicAdd(&psum[b * DD + col], sum[nt][j]);
                    atomicMax(&pmax[b * DD + col], fkey(mx[nt][j]));
                }
        }
    }
}

// =================================================================
// Fused flash attention (unchanged).
// =================================================================
__global__ void __launch_bounds__(256)
flash_k(const bf16* __restrict__ Qh, const bf16* __restrict__ Ql,
        const bf16* __restrict__ Kh, const bf16* __restrict__ Kl,
        const h16* __restrict__ V, h16* __restrict__ O_)
{
    extern __shared__ __align__(16) char sm[];
    constexpr int QS = 128 * 136;
    constexpr int TS = 64 * 136;
    bf16* sQh = (bf16*)sm;
    bf16* sQl = sQh + QS;
    char* sT  = (char*)(sQl + QS);
    constexpr long STG = 3L * TS * 2;

    const int bh = blockIdx.y, b = bh >> 3, h = bh & 7;
    const int q0 = blockIdx.x * 128;
    const int u = threadIdx.x, wid = u >> 5, lane = u & 31;
    const int tr = lane >> 2, tc = lane & 3;

    const long qg = ((long)b * LL + q0) * DD + h * KHD;
    const long kg = (long)b * LL * DD + h * KHD;

    for (int c = u; c < 2048; c += 256) {
        const int r = c >> 4, s = (c & 15) * 8;
        cpa16(sQh + r * 136 + s, Qh + qg + (long)r * DD + s);
        cpa16(sQl + r * 136 + s, Ql + qg + (long)r * DD + s);
    }
    auto stage = [&](int buf, int kv0) {
        bf16* pKh = (bf16*)(sT + buf * STG);
        bf16* pKl = pKh + TS;
        h16*  pV  = (h16*)(pKl + TS);
        for (int c = u; c < 1024; c += 256) {
            const int r = c >> 4, s = (c & 15) * 8;
            const long g = kg + (long)(kv0 + r) * DD + s;
            cpa16(pKh + r * 136 + s, Kh + g);
            cpa16(pKl + r * 136 + s, Kl + g);
            cpa16(pV  + r * 136 + s, V + g);
        }
    };
    stage(0, 0);
    cp_commit();

    float O[16][4];
    #pragma unroll
    for (int i = 0; i < 16; ++i)
        #pragma unroll
        for (int j = 0; j < 4; ++j) O[i][j] = 0.f;
    float m0 = -1e30f, m1 = -1e30f, l0 = 0.f, l1 = 0.f;

    const int brow = ((lane >> 4) & 1) * 8 + (lane & 7);
    const int bcol = ((lane >> 3) & 1) * 8;
    const int vrow = ((lane >> 3) & 1) * 8 + (lane & 7);
    const int vsel = (lane >> 4);

    for (int t = 0; t < 16; ++t) {
        if (t + 1 < 16) stage((t + 1) & 1, (t + 1) * 64);
        cp_commit();
        cp_wait1();
        __syncthreads();

        const bf16* cKh = (const bf16*)(sT + (t & 1) * STG);
        const bf16* cKl = cKh + TS;
        const h16*  cV  = (const h16*)(cKl + TS);

        float S[8][4];
        #pragma unroll
        for (int i = 0; i < 8; ++i)
            #pragma unroll
            for (int j = 0; j < 4; ++j) S[i][j] = 0.f;

        #pragma unroll
        for (int kk = 0; kk < 128; kk += 16) {
            uint32_t ah[4], al[4];
            const int aoff = (wid * 16 + (lane & 15)) * 136 + kk + (lane >> 4) * 8;
            ldsm_x4(ah, sQh + aoff);
            ldsm_x4(al, sQl + aoff);
            #pragma unroll
            for (int np = 0; np < 4; ++np) {
                uint32_t bh4[4], bl4[4];
                const int boff = (np * 16 + brow) * 136 + kk + bcol;
                ldsm_x4(bh4, cKh + boff);
                ldsm_x4(bl4, cKl + boff);
                #pragma unroll
                for (int half = 0; half < 2; ++half) {
                    float* s_ = S[np * 2 + half];
                    mma_bf16(s_, ah, bh4 + half * 2);
                    mma_bf16(s_, ah, bl4 + half * 2);
                    mma_bf16(s_, al, bh4 + half * 2);
                }
            }
        }

        float rm0 = -1e30f, rm1 = -1e30f;
        #pragma unroll
        for (int nt = 0; nt < 8; ++nt) {
            rm0 = fmaxf(rm0, fmaxf(S[nt][0], S[nt][1]));
            rm1 = fmaxf(rm1, fmaxf(S[nt][2], S[nt][3]));
        }
        rm0 = fmaxf(rm0, __shfl_xor_sync(~0u, rm0, 1));
        rm0 = fmaxf(rm0, __shfl_xor_sync(~0u, rm0, 2));
        rm1 = fmaxf(rm1, __shfl_xor_sync(~0u, rm1, 1));
        rm1 = fmaxf(rm1, __shfl_xor_sync(~0u, rm1, 2));
        const float M0 = fmaxf(m0, rm0), M1 = fmaxf(m1, rm1);
        const float f0 = __expf(m0 - M0), f1 = __expf(m1 - M1);
        m0 = M0; m1 = M1;
        l0 *= f0; l1 *= f1;
        #pragma unroll
        for (int dt = 0; dt < 16; ++dt) {
            O[dt][0] *= f0; O[dt][1] *= f0;
            O[dt][2] *= f1; O[dt][3] *= f1;
        }

        #pragma unroll
        for (int kc = 0; kc < 4; ++kc) {
            uint32_t pa[4];
            #pragma unroll
            for (int half = 0; half < 2; ++half) {
                const int nt = kc * 2 + half;
                const float p0 = __expf(S[nt][0] - M0);
                const float p1 = __expf(S[nt][1] - M0);
                const float p2 = __expf(S[nt][2] - M1);
                const float p3 = __expf(S[nt][3] - M1);
                l0 += p0 + p1; l1 += p2 + p3;
                pa[half ? 2 : 0] = pkh(__float2half_rn(p0), __float2half_rn(p1));
                pa[half ? 3 : 1] = pkh(__float2half_rn(p2), __float2half_rn(p3));
            }
            #pragma unroll
            for (int dt = 0; dt < 16; dt += 2) {
                uint32_t bv[4];
                const int voff = (kc * 16 + vrow) * 136 + (dt + vsel) * 8;
                ldsm_x4t(bv, cV + voff);
                mma_f16(O[dt],     pa, bv);
                mma_f16(O[dt + 1], pa, bv + 2);
            }
        }
        __syncthreads();
    }

    l0 += __shfl_xor_sync(~0u, l0, 1); l0 += __shfl_xor_sync(~0u, l0, 2);
    l1 += __shfl_xor_sync(~0u, l1, 1); l1 += __shfl_xor_sync(~0u, l1, 2);
    const float i0 = 1.f / l0, i1 = 1.f / l1;
    const long og = ((long)b * LL + q0 + wid * 16) * DD + h * KHD;
    #pragma unroll
    for (int dt = 0; dt < 16; ++dt) {
        const int col = dt * 8 + tc * 2;
        *(uint32_t*)&O_[og + (long)tr * DD + col] =
            pkh(__float2half_rn(O[dt][0] * i0), __float2half_rn(O[dt][1] * i0));
        *(uint32_t*)&O_[og + (long)(tr + 8) * DD + col] =
            pkh(__float2half_rn(O[dt][2] * i1), __float2half_rn(O[dt][3] * i1));
    }
}

// ---------------- fused converts ----------------
__device__ __forceinline__ void split4_b(const float* in, bf16* hi, bf16* lo, int i)
{
    const float4 v = ((const float4*)in)[i];
    bf16 h0, l0, h1, l1, h2, l2, h3, l3;
    bsplit(v.x, h0, l0); bsplit(v.y, h1, l1);
    bsplit(v.z, h2, l2); bsplit(v.w, h3, l3);
    ((uint32_t*)hi)[i * 2]     = pkb(h0, h1);
    ((uint32_t*)hi)[i * 2 + 1] = pkb(h2, h3);
    ((uint32_t*)lo)[i * 2]     = pkb(l0, l1);
    ((uint32_t*)lo)[i * 2 + 1] = pkb(l2, l3);
}
__device__ __forceinline__ void conv4_h(const float* in, h16* hi, int i)
{
    const float4 v = ((const float4*)in)[i];
    ((uint32_t*)hi)[i * 2]     = pkh(__float2half_rn(v.x), __float2half_rn(v.y));
    ((uint32_t*)hi)[i * 2 + 1] = pkh(__float2half_rn(v.z), __float2half_rn(v.w));
}

__global__ void conv_x(const float* __restrict__ x1, bf16* __restrict__ x1h, bf16* __restrict__ x1l,
                       const float* __restrict__ x2, bf16* __restrict__ x2h, bf16* __restrict__ x2l,
                       const float* __restrict__ x0, h16* __restrict__ x0h)
{
    const int i = blockIdx.x * 256 + threadIdx.x;
    switch (blockIdx.y) {
        case 0: split4_b(x1, x1h, x1l, i); break;
        case 1: split4_b(x2, x2h, x2l, i); break;
        default: conv4_h(x0, x0h, i); break;
    }
}
__global__ void conv_w(const float* __restrict__ Wk, bf16* __restrict__ wkh, bf16* __restrict__ wkl,
                       const float* __restrict__ Wq, bf16* __restrict__ wqh, bf16* __restrict__ wql,
                       const float* __restrict__ Wv, h16* __restrict__ wvh,
                       const float* __restrict__ Wu, h16* __restrict__ wuh)
{
    const int i = blockIdx.x * 256 + threadIdx.x;
    switch (blockIdx.y) {
        case 0: split4_b(Wk, wkh, wkl, i); break;
        case 1: split4_b(Wq, wqh, wql, i); break;
        case 2: conv4_h(Wv, wvh, i); break;
        default: conv4_h(Wu, wuh, i); break;
    }
}

// ---------------- pool init + logits ----------------
__global__ void init_pool(float* __restrict__ psum, unsigned* __restrict__ pmax)
{
    const int i = blockIdx.x * 256 + threadIdx.x;
    if (i < BB * DD) { psum[i] = 0.f; pmax[i] = 0u; }
}

__global__ void logits_kernel(const float* __restrict__ psum,
                              const unsigned* __restrict__ pmax,
                              const float* __restrict__ Wm,
                              const float* __restrict__ bm,
                              float* __restrict__ out)
{
    const int b = blockIdx.x;
    __shared__ float ps[DD];
    __shared__ float red[4][OUTN];
    for (int i = threadIdx.x; i < DD; i += 256)
        ps[i] = psum[b * DD + i] * (1.f / LL) + fdec(pmax[b * DD + i]);
    __syncthreads();
    const int o = threadIdx.x & 63, part = threadIdx.x >> 6;
    float s = 0.f;
    const float* w = Wm + (long)o * DD + part * 256;
    const float* p = ps + part * 256;
    #pragma unroll 8
    for (int kk = 0; kk < 256; ++kk) s += p[kk] * w[kk];
    red[part][o] = s;
    __syncthreads();
    if (part == 0)
        out[b * OUTN + o] = red[0][o] + red[1][o] + red[2][o] + red[3][o] + bm[o];
}

// =================================================================
extern "C" void kernel_launch(void* const* d_in, const int* in_sizes, int n_in,
                              void* d_out, int out_size)
{
    const float* x0   = (const float*)d_in[0];
    const float* x1   = (const float*)d_in[1];
    const float* x2   = (const float*)d_in[2];
    const float* Wk   = (const float*)d_in[5];
    const float* Wq   = (const float*)d_in[6];
    const float* Wv   = (const float*)d_in[7];
    const float* Wu   = (const float*)d_in[8];
    const float* bu   = (const float*)d_in[9];
    const float* Wmlp = (const float*)d_in[10];
    const float* bmlp = (const float*)d_in[11];
    float* out = (float*)d_out;

    bf16 *x1h,*x1l,*x2h,*x2l,*wkh,*wkl,*wqh,*wql,*qh,*ql,*kh,*kl;
    h16  *x0h,*wvh,*wuh,*vv,*att;
    float *psum; unsigned *pmax;
    cudaGetSymbolAddress((void**)&x1h, g_x1h); cudaGetSymbolAddress((void**)&x1l, g_x1l);
    cudaGetSymbolAddress((void**)&x2h, g_x2h); cudaGetSymbolAddress((void**)&x2l, g_x2l);
    cudaGetSymbolAddress((void**)&wkh, g_wkh); cudaGetSymbolAddress((void**)&wkl, g_wkl);
    cudaGetSymbolAddress((void**)&wqh, g_wqh); cudaGetSymbolAddress((void**)&wql, g_wql);
    cudaGetSymbolAddress((void**)&qh,  g_qh);  cudaGetSymbolAddress((void**)&ql,  g_ql);
    cudaGetSymbolAddress((void**)&kh,  g_kh);  cudaGetSymbolAddress((void**)&kl,  g_kl);
    cudaGetSymbolAddress((void**)&x0h, g_x0h);
    cudaGetSymbolAddress((void**)&wvh, g_wvh);
    cudaGetSymbolAddress((void**)&wuh, g_wuh);
    cudaGetSymbolAddress((void**)&vv,  g_vv);  cudaGetSymbolAddress((void**)&att, g_att);
    cudaGetSymbolAddress((void**)&psum, g_psum);
    cudaGetSymbolAddress((void**)&pmax, g_pmax);

    const float scale = powf((float)KHD, -0.25f);
    const int M = BB * LL;

    constexpr int SM_B3 = 4 * (2 * 128 * 24 + 2 * 256 * 24) * 2;   // 147456
    constexpr int SM_H1 = 4 * (128 * 24 + 256 * 24) * 2;           // 73728
    constexpr int SM_FL = 2*128*136*2 + 2*3*64*136*2;              // 174080
    cudaFuncSetAttribute(gemm_b3,    cudaFuncAttributeMaxDynamicSharedMemorySize, SM_B3);
    cudaFuncSetAttribute(gemm_h1<0>, cudaFuncAttributeMaxDynamicSharedMemorySize, SM_H1);
    cudaFuncSetAttribute(gemm_h1<1>, cudaFuncAttributeMaxDynamicSharedMemorySize, SM_H1);
    cudaFuncSetAttribute(flash_k,    cudaFuncAttributeMaxDynamicSharedMemorySize, SM_FL);

    // --- converts ---
    {
        dim3 gx(BB * LL * DD / 4 / 256, 3);
        conv_x<<<gx, 256>>>(x1, x1h, x1l, x2, x2h, x2l, x0, x0h);
        dim3 gw(DD * DD / 4 / 256, 4);
        conv_w<<<gw, 256>>>(Wk, wkh, wkl, Wq, wqh, wql, Wv, wvh, Wu, wuh);
    }
    init_pool<<<(BB * DD + 255) / 256, 256>>>(psum, pmax);

    dim3 blk(256);

    // --- q & k projections (z=2) + v ---
    {
        dim3 g2(DD / 256, M / 128, 2);
        gemm_b3<<<g2, blk, SM_B3>>>(x2h, x2l, wkh, wkl, qh, ql,
                                    x1h, x1l, wqh, wql, kh, kl, scale);
        dim3 g1(DD / 256, M / 128);
        gemm_h1<0><<<g1, blk, SM_H1>>>(x0h, wvh, vv, nullptr, nullptr, nullptr);
    }

    // --- fused attention ---
    {
        dim3 grid(LL / 128, BB * HH);
        flash_k<<<grid, blk, SM_FL>>>(qh, ql, kh, kl, vv, att);
    }

    // --- unify (1-MMA) + fused pooling ---
    {
        dim3 g1(DD / 256, M / 128);
        gemm_h1<1><<<g1, blk, SM_H1>>>(att, wuh, nullptr, bu, psum, pmax);
    }

    // --- logits ---
    logits_kernel<<<BB, 256>>>(psum, pmax, Wmlp, bmlp, out);
}

// round 12
// speedup vs baseline: 1.3387x; 1.3387x over previous
#include <cuda_runtime.h>
#include <cuda_bf16.h>
#include <cuda_fp16.h>
#include <math.h>
#include <stdint.h>

#define BB 16
#define LL 1024
#define DD 1024
#define HH 8
#define KHD 128
#define OUTN 64

typedef __nv_bfloat16  bf16;
typedef __nv_bfloat162 bf162;
typedef __half  h16;
typedef __half2 h162;

// ---------------- scratch ----------------
__device__ h16 g_x1h[BB*LL*DD];
__device__ h16 g_x2h[BB*LL*DD];
__device__ h16 g_x0h[BB*LL*DD];
__device__ h16 g_wkh[DD*DD], g_wkl[DD*DD];
__device__ h16 g_wqh[DD*DD], g_wql[DD*DD];
__device__ h16 g_wvh[DD*DD];
__device__ h16 g_wuh[DD*DD];
__device__ bf16 g_qh[BB*LL*DD], g_ql[BB*LL*DD];
__device__ bf16 g_kh[BB*LL*DD], g_kl[BB*LL*DD];
__device__ h16 g_vv [BB*LL*DD];
__device__ h16 g_att[BB*LL*DD];
__device__ float    g_psum[BB*DD];
__device__ unsigned g_pmax[BB*DD];

// ---------------- helpers ----------------
__device__ __forceinline__ void bsplit(float x, bf16& h, bf16& l) {
    h = __float2bfloat16_rn(x);
    l = __float2bfloat16_rn(x - __bfloat162float(h));
}
__device__ __forceinline__ void hsplit(float x, h16& h, h16& l) {
    h = __float2half_rn(x);
    l = __float2half_rn(x - __half2float(h));
}
__device__ __forceinline__ uint32_t pkb(bf16 x, bf16 y) {
    bf162 t; t.x = x; t.y = y; return *(uint32_t*)&t;
}
__device__ __forceinline__ uint32_t pkh(h16 x, h16 y) {
    h162 t; t.x = x; t.y = y; return *(uint32_t*)&t;
}
__device__ __forceinline__ void cpa16(void* s, const void* g) {
    uint32_t sa = (uint32_t)__cvta_generic_to_shared(s);
    asm volatile("cp.async.cg.shared.global [%0], [%1], 16;" :: "r"(sa), "l"(g));
}
__device__ __forceinline__ void cp_commit() {
    asm volatile("cp.async.commit_group;" ::: "memory");
}
__device__ __forceinline__ void cp_wait1() {
    asm volatile("cp.async.wait_group 1;" ::: "memory");
}
__device__ __forceinline__ void cp_wait2() {
    asm volatile("cp.async.wait_group 2;" ::: "memory");
}
__device__ __forceinline__ void ldsm_x4(uint32_t* r, const void* p) {
    uint32_t a = (uint32_t)__cvta_generic_to_shared(p);
    asm volatile("ldmatrix.sync.aligned.m8n8.x4.shared.b16 {%0,%1,%2,%3}, [%4];"
        : "=r"(r[0]), "=r"(r[1]), "=r"(r[2]), "=r"(r[3]) : "r"(a));
}
__device__ __forceinline__ void ldsm_x4t(uint32_t* r, const void* p) {
    uint32_t a = (uint32_t)__cvta_generic_to_shared(p);
    asm volatile("ldmatrix.sync.aligned.m8n8.x4.trans.shared.b16 {%0,%1,%2,%3}, [%4];"
        : "=r"(r[0]), "=r"(r[1]), "=r"(r[2]), "=r"(r[3]) : "r"(a));
}
__device__ __forceinline__ void mma_bf16(float* c, const uint32_t* a, const uint32_t* b) {
    asm volatile(
        "mma.sync.aligned.m16n8k16.row.col.f32.bf16.bf16.f32 "
        "{%0,%1,%2,%3},{%4,%5,%6,%7},{%8,%9},{%0,%1,%2,%3};"
        : "+f"(c[0]), "+f"(c[1]), "+f"(c[2]), "+f"(c[3])
        : "r"(a[0]), "r"(a[1]), "r"(a[2]), "r"(a[3]), "r"(b[0]), "r"(b[1]));
}
__device__ __forceinline__ void mma_f16(float* c, const uint32_t* a, const uint32_t* b) {
    asm volatile(
        "mma.sync.aligned.m16n8k16.row.col.f32.f16.f16.f32 "
        "{%0,%1,%2,%3},{%4,%5,%6,%7},{%8,%9},{%0,%1,%2,%3};"
        : "+f"(c[0]), "+f"(c[1]), "+f"(c[2]), "+f"(c[3])
        : "r"(a[0]), "r"(a[1]), "r"(a[2]), "r"(a[3]), "r"(b[0]), "r"(b[1]));
}
__device__ __forceinline__ unsigned fkey(float v) {
    unsigned u = __float_as_uint(v);
    return (u & 0x80000000u) ? ~u : (u | 0x80000000u);
}
__device__ __forceinline__ float fdec(unsigned k) {
    unsigned u = (k & 0x80000000u) ? (k ^ 0x80000000u) : ~k;
    return __uint_as_float(u);
}

// =================================================================
// q/k projections: fp16 2-MMA TN GEMM, z-batched over {q,k}.
// A = x (fp16 single), B = W (split fp16). BM=BN=128, BK=16,
// 4-stage cp.async, warp tile 64x32, 2 CTA/SM.
// C = alpha * A @ B^T, written split-bf16.
// =================================================================
__global__ void __launch_bounds__(256, 2)
gemm_qk(const h16* __restrict__ A0, const h16* __restrict__ B0h,
        const h16* __restrict__ B0l, bf16* __restrict__ C0h, bf16* __restrict__ C0l,
        const h16* __restrict__ A1, const h16* __restrict__ B1h,
        const h16* __restrict__ B1l, bf16* __restrict__ C1h, bf16* __restrict__ C1l,
        float alpha)
{
    extern __shared__ __align__(16) char smem[];
    constexpr int RS  = 24;
    constexpr int ARR = 128 * RS;
    constexpr int STG = 3 * ARR;

    const h16* Ax = blockIdx.z ? A1 : A0;
    const h16* Bh = blockIdx.z ? B1h : B0h;
    const h16* Bl = blockIdx.z ? B1l : B0l;
    bf16* Ch = blockIdx.z ? C1h : C0h;
    bf16* Cl = blockIdx.z ? C1l : C0l;

    const int bm = blockIdx.y * 128, bn = blockIdx.x * 128;
    const int u = threadIdx.x, wid = u >> 5, lane = u & 31;
    const int wm = (wid >> 2) * 64, wn = (wid & 3) * 32;

    float acc[4][4][4];
    #pragma unroll
    for (int i = 0; i < 4; ++i)
        #pragma unroll
        for (int j = 0; j < 4; ++j)
            #pragma unroll
            for (int p = 0; p < 4; ++p) acc[i][j][p] = 0.f;

    const int srow = u >> 1, shalf = (u & 1) * 8;
    auto stage = [&](int buf, int k0) {
        h16* s0 = (h16*)smem + (long)buf * STG + srow * RS + shalf;
        const long ga = (long)(bm + srow) * DD + k0 + shalf;
        const long gb = (long)(bn + srow) * DD + k0 + shalf;
        cpa16(s0,           Ax + ga);
        cpa16(s0 + ARR,     Bh + gb);
        cpa16(s0 + 2 * ARR, Bl + gb);
    };

    constexpr int nst = DD / 16;
    #pragma unroll
    for (int t = 0; t < 3; ++t) { stage(t, t * 16); cp_commit(); }

    const int arow = lane & 15, asel = (lane >> 4) * 8;
    const int brow = ((lane >> 4) & 1) * 8 + (lane & 7);
    const int bcol = ((lane >> 3) & 1) * 8;

    for (int s = 0; s < nst; ++s) {
        cp_wait2();
        __syncthreads();
        if (s + 3 < nst) stage((s + 3) & 3, (s + 3) * 16);
        cp_commit();

        const h16* base = (const h16*)smem + (long)(s & 3) * STG;
        const h16* sA  = base;
        const h16* sBh = base + ARR;
        const h16* sBl = base + 2 * ARR;

        uint32_t ah[4][4];
        #pragma unroll
        for (int mt = 0; mt < 4; ++mt)
            ldsm_x4(ah[mt], sA + (wm + mt * 16 + arow) * RS + asel);
        #pragma unroll
        for (int np = 0; np < 2; ++np) {
            uint32_t bh4[4], bl4[4];
            const int off = (wn + np * 16 + brow) * RS + bcol;
            ldsm_x4(bh4, sBh + off);
            ldsm_x4(bl4, sBl + off);
            #pragma unroll
            for (int half = 0; half < 2; ++half) {
                const int nt = np * 2 + half;
                #pragma unroll
                for (int mt = 0; mt < 4; ++mt) {
                    mma_f16(acc[mt][nt], ah[mt], bh4 + half * 2);
                    mma_f16(acc[mt][nt], ah[mt], bl4 + half * 2);
                }
            }
        }
    }

    const int tr = lane >> 2, tc = lane & 3;
    #pragma unroll
    for (int mt = 0; mt < 4; ++mt) {
        const int row = bm + wm + mt * 16 + tr;
        #pragma unroll
        for (int nt = 0; nt < 4; ++nt) {
            const int col = bn + wn + nt * 8 + tc * 2;
            const float* c = acc[mt][nt];
            bf16 h0, l0, h1, l1;
            bsplit(c[0] * alpha, h0, l0); bsplit(c[1] * alpha, h1, l1);
            *(uint32_t*)&Ch[(long)row * DD + col] = pkb(h0, h1);
            *(uint32_t*)&Cl[(long)row * DD + col] = pkb(l0, l1);
            bsplit(c[2] * alpha, h0, l0); bsplit(c[3] * alpha, h1, l1);
            *(uint32_t*)&Ch[(long)(row + 8) * DD + col] = pkb(h0, h1);
            *(uint32_t*)&Cl[(long)(row + 8) * DD + col] = pkb(l0, l1);
        }
    }
}

// =================================================================
// fp16 1-MMA TN GEMM (R10 geometry). POOL 0: fp16 C; POOL 1: pooling.
// =================================================================
template<int POOL>
__global__ void __launch_bounds__(256, 2)
gemm_h1(const h16* __restrict__ Ax, const h16* __restrict__ Bh,
        h16* __restrict__ Chf, const float* __restrict__ bias,
        float* __restrict__ psum, unsigned* __restrict__ pmax)
{
    extern __shared__ __align__(16) char smem[];
    constexpr int RS  = 24;
    constexpr int ARR = 128 * RS;
    constexpr int STG = 2 * ARR;

    const int bm = blockIdx.y * 128, bn = blockIdx.x * 128;
    const int u = threadIdx.x, wid = u >> 5, lane = u & 31;
    const int wm = (wid >> 2) * 64, wn = (wid & 3) * 32;

    float acc[4][4][4];
    #pragma unroll
    for (int i = 0; i < 4; ++i)
        #pragma unroll
        for (int j = 0; j < 4; ++j)
            #pragma unroll
            for (int p = 0; p < 4; ++p) acc[i][j][p] = 0.f;

    const int srow = u >> 1, shalf = (u & 1) * 8;
    auto stage = [&](int buf, int k0) {
        h16* s0 = (h16*)smem + (long)buf * STG + srow * RS + shalf;
        cpa16(s0,       Ax + (long)(bm + srow) * DD + k0 + shalf);
        cpa16(s0 + ARR, Bh + (long)(bn + srow) * DD + k0 + shalf);
    };

    constexpr int nst = DD / 16;
    #pragma unroll
    for (int t = 0; t < 3; ++t) { stage(t, t * 16); cp_commit(); }

    const int arow = lane & 15, asel = (lane >> 4) * 8;
    const int brow = ((lane >> 4) & 1) * 8 + (lane & 7);
    const int bcol = ((lane >> 3) & 1) * 8;

    for (int s = 0; s < nst; ++s) {
        cp_wait2();
        __syncthreads();
        if (s + 3 < nst) stage((s + 3) & 3, (s + 3) * 16);
        cp_commit();

        const h16* base = (const h16*)smem + (long)(s & 3) * STG;
        const h16* sA  = base;
        const h16* sBh = base + ARR;

        uint32_t ah[4][4];
        #pragma unroll
        for (int mt = 0; mt < 4; ++mt)
            ldsm_x4(ah[mt], sA + (wm + mt * 16 + arow) * RS + asel);
        #pragma unroll
        for (int np = 0; np < 2; ++np) {
            uint32_t bh4[4];
            ldsm_x4(bh4, sBh + (wn + np * 16 + brow) * RS + bcol);
            #pragma unroll
            for (int half = 0; half < 2; ++half) {
                const int nt = np * 2 + half;
                #pragma unroll
                for (int mt = 0; mt < 4; ++mt)
                    mma_f16(acc[mt][nt], ah[mt], bh4 + half * 2);
            }
        }
    }

    const int tr = lane >> 2, tc = lane & 3;
    if (POOL == 0) {
        #pragma unroll
        for (int mt = 0; mt < 4; ++mt) {
            const int row = bm + wm + mt * 16 + tr;
            #pragma unroll
            for (int nt = 0; nt < 4; ++nt) {
                const int col = bn + wn + nt * 8 + tc * 2;
                const float* c = acc[mt][nt];
                *(uint32_t*)&Chf[(long)row * DD + col] =
                    pkh(__float2half_rn(c[0]), __float2half_rn(c[1]));
                *(uint32_t*)&Chf[(long)(row + 8) * DD + col] =
                    pkh(__float2half_rn(c[2]), __float2half_rn(c[3]));
            }
        }
    } else {
        const int b = bm >> 10;
        float sum[4][2], mx[4][2];
        #pragma unroll
        for (int nt = 0; nt < 4; ++nt) {
            #pragma unroll
            for (int j = 0; j < 2; ++j) {
                const int col = bn + wn + nt * 8 + tc * 2 + j;
                const float bv = __ldg(bias + col);
                float s_ = 0.f, m_ = -1e30f;
                #pragma unroll
                for (int mt = 0; mt < 4; ++mt) {
                    const float v0 = acc[mt][nt][j] + bv;
                    const float v1 = acc[mt][nt][j + 2] + bv;
                    s_ += v0 + v1;
                    m_ = fmaxf(m_, fmaxf(v0, v1));
                }
                sum[nt][j] = s_; mx[nt][j] = m_;
            }
        }
        #pragma unroll
        for (int o = 4; o <= 16; o <<= 1) {
            #pragma unroll
            for (int nt = 0; nt < 4; ++nt)
                #pragma unroll
                for (int j = 0; j < 2; ++j) {
                    sum[nt][j] += __shfl_xor_sync(~0u, sum[nt][j], o);
                    mx[nt][j] = fmaxf(mx[nt][j], __shfl_xor_sync(~0u, mx[nt][j], o));
                }
        }
        if (tr == 0) {
            #pragma unroll
            for (int nt = 0; nt < 4; ++nt)
                #pragma unroll
                for (int j = 0; j < 2; ++j) {
                    const int col = bn + wn + nt * 8 + tc * 2 + j;
                    atomicAdd(&psum[b * DD + col], sum[nt][j]);
                    atomicMax(&pmax[b * DD + col], fkey(mx[nt][j]));
                }
        }
    }
}

// =================================================================
// Fused flash attention (R10 version, unchanged).
// =================================================================
__global__ void __launch_bounds__(256)
flash_k(const bf16* __restrict__ Qh, const bf16* __restrict__ Ql,
        const bf16* __restrict__ Kh, const bf16* __restrict__ Kl,
        const h16* __restrict__ V, h16* __restrict__ O_)
{
    extern __shared__ __align__(16) char sm[];
    constexpr int QS = 128 * 136;
    constexpr int TS = 64 * 136;
    bf16* sQh = (bf16*)sm;
    bf16* sQl = sQh + QS;
    char* sT  = (char*)(sQl + QS);
    constexpr long STG = 3L * TS * 2;

    const int bh = blockIdx.y, b = bh >> 3, h = bh & 7;
    const int q0 = blockIdx.x * 128;
    const int u = threadIdx.x, wid = u >> 5, lane = u & 31;
    const int tr = lane >> 2, tc = lane & 3;

    const long qg = ((long)b * LL + q0) * DD + h * KHD;
    const long kg = (long)b * LL * DD + h * KHD;

    for (int c = u; c < 2048; c += 256) {
        const int r = c >> 4, s = (c & 15) * 8;
        cpa16(sQh + r * 136 + s, Qh + qg + (long)r * DD + s);
        cpa16(sQl + r * 136 + s, Ql + qg + (long)r * DD + s);
    }
    auto stage = [&](int buf, int kv0) {
        bf16* pKh = (bf16*)(sT + buf * STG);
        bf16* pKl = pKh + TS;
        h16*  pV  = (h16*)(pKl + TS);
        for (int c = u; c < 1024; c += 256) {
            const int r = c >> 4, s = (c & 15) * 8;
            const long g = kg + (long)(kv0 + r) * DD + s;
            cpa16(pKh + r * 136 + s, Kh + g);
            cpa16(pKl + r * 136 + s, Kl + g);
            cpa16(pV  + r * 136 + s, V + g);
        }
    };
    stage(0, 0);
    cp_commit();

    float O[16][4];
    #pragma unroll
    for (int i = 0; i < 16; ++i)
        #pragma unroll
        for (int j = 0; j < 4; ++j) O[i][j] = 0.f;
    float m0 = -1e30f, m1 = -1e30f, l0 = 0.f, l1 = 0.f;

    const int brow = ((lane >> 4) & 1) * 8 + (lane & 7);
    const int bcol = ((lane >> 3) & 1) * 8;
    const int vrow = ((lane >> 3) & 1) * 8 + (lane & 7);
    const int vsel = (lane >> 4);

    for (int t = 0; t < 16; ++t) {
        if (t + 1 < 16) stage((t + 1) & 1, (t + 1) * 64);
        cp_commit();
        cp_wait1();
        __syncthreads();

        const bf16* cKh = (const bf16*)(sT + (t & 1) * STG);
        const bf16* cKl = cKh + TS;
        const h16*  cV  = (const h16*)(cKl + TS);

        float S[8][4];
        #pragma unroll
        for (int i = 0; i < 8; ++i)
            #pragma unroll
            for (int j = 0; j < 4; ++j) S[i][j] = 0.f;

        #pragma unroll
        for (int kk = 0; kk < 128; kk += 16) {
            uint32_t ah[4], al[4];
            const int aoff = (wid * 16 + (lane & 15)) * 136 + kk + (lane >> 4) * 8;
            ldsm_x4(ah, sQh + aoff);
            ldsm_x4(al, sQl + aoff);
            #pragma unroll
            for (int np = 0; np < 4; ++np) {
                uint32_t bh4[4], bl4[4];
                const int boff = (np * 16 + brow) * 136 + kk + bcol;
                ldsm_x4(bh4, cKh + boff);
                ldsm_x4(bl4, cKl + boff);
                #pragma unroll
                for (int half = 0; half < 2; ++half) {
                    float* s_ = S[np * 2 + half];
                    mma_bf16(s_, ah, bh4 + half * 2);
                    mma_bf16(s_, ah, bl4 + half * 2);
                    mma_bf16(s_, al, bh4 + half * 2);
                }
            }
        }

        float rm0 = -1e30f, rm1 = -1e30f;
        #pragma unroll
        for (int nt = 0; nt < 8; ++nt) {
            rm0 = fmaxf(rm0, fmaxf(S[nt][0], S[nt][1]));
            rm1 = fmaxf(rm1, fmaxf(S[nt][2], S[nt][3]));
        }
        rm0 = fmaxf(rm0, __shfl_xor_sync(~0u, rm0, 1));
        rm0 = fmaxf(rm0, __shfl_xor_sync(~0u, rm0, 2));
        rm1 = fmaxf(rm1, __shfl_xor_sync(~0u, rm1, 1));
        rm1 = fmaxf(rm1, __shfl_xor_sync(~0u, rm1, 2));
        const float M0 = fmaxf(m0, rm0), M1 = fmaxf(m1, rm1);
        const float f0 = __expf(m0 - M0), f1 = __expf(m1 - M1);
        m0 = M0; m1 = M1;
        l0 *= f0; l1 *= f1;
        #pragma unroll
        for (int dt = 0; dt < 16; ++dt) {
            O[dt][0] *= f0; O[dt][1] *= f0;
            O[dt][2] *= f1; O[dt][3] *= f1;
        }

        #pragma unroll
        for (int kc = 0; kc < 4; ++kc) {
            uint32_t pa[4];
            #pragma unroll
            for (int half = 0; half < 2; ++half) {
                const int nt = kc * 2 + half;
                const float p0 = __expf(S[nt][0] - M0);
                const float p1 = __expf(S[nt][1] - M0);
                const float p2 = __expf(S[nt][2] - M1);
                const float p3 = __expf(S[nt][3] - M1);
                l0 += p0 + p1; l1 += p2 + p3;
                pa[half ? 2 : 0] = pkh(__float2half_rn(p0), __float2half_rn(p1));
                pa[half ? 3 : 1] = pkh(__float2half_rn(p2), __float2half_rn(p3));
            }
            #pragma unroll
            for (int dt = 0; dt < 16; dt += 2) {
                uint32_t bv[4];
                const int voff = (kc * 16 + vrow) * 136 + (dt + vsel) * 8;
                ldsm_x4t(bv, cV + voff);
                mma_f16(O[dt],     pa, bv);
                mma_f16(O[dt + 1], pa, bv + 2);
            }
        }
        __syncthreads();
    }

    l0 += __shfl_xor_sync(~0u, l0, 1); l0 += __shfl_xor_sync(~0u, l0, 2);
    l1 += __shfl_xor_sync(~0u, l1, 1); l1 += __shfl_xor_sync(~0u, l1, 2);
    const float i0 = 1.f / l0, i1 = 1.f / l1;
    const long og = ((long)b * LL + q0 + wid * 16) * DD + h * KHD;
    #pragma unroll
    for (int dt = 0; dt < 16; ++dt) {
        const int col = dt * 8 + tc * 2;
        *(uint32_t*)&O_[og + (long)tr * DD + col] =
            pkh(__float2half_rn(O[dt][0] * i0), __float2half_rn(O[dt][1] * i0));
        *(uint32_t*)&O_[og + (long)(tr + 8) * DD + col] =
            pkh(__float2half_rn(O[dt][2] * i1), __float2half_rn(O[dt][3] * i1));
    }
}

// ---------------- converts ----------------
__device__ __forceinline__ void split4_h(const float* in, h16* hi, h16* lo, int i)
{
    const float4 v = ((const float4*)in)[i];
    h16 h0, l0, h1, l1, h2, l2, h3, l3;
    hsplit(v.x, h0, l0); hsplit(v.y, h1, l1);
    hsplit(v.z, h2, l2); hsplit(v.w, h3, l3);
    ((uint32_t*)hi)[i * 2]     = pkh(h0, h1);
    ((uint32_t*)hi)[i * 2 + 1] = pkh(h2, h3);
    ((uint32_t*)lo)[i * 2]     = pkh(l0, l1);
    ((uint32_t*)lo)[i * 2 + 1] = pkh(l2, l3);
}
__device__ __forceinline__ void conv4_h(const float* in, h16* hi, int i)
{
    const float4 v = ((const float4*)in)[i];
    ((uint32_t*)hi)[i * 2]     = pkh(__float2half_rn(v.x), __float2half_rn(v.y));
    ((uint32_t*)hi)[i * 2 + 1] = pkh(__float2half_rn(v.z), __float2half_rn(v.w));
}

__global__ void conv_x(const float* __restrict__ x1, h16* __restrict__ x1h,
                       const float* __restrict__ x2, h16* __restrict__ x2h,
                       const float* __restrict__ x0, h16* __restrict__ x0h)
{
    const int i = blockIdx.x * 256 + threadIdx.x;
    switch (blockIdx.y) {
        case 0: conv4_h(x1, x1h, i); break;
        case 1: conv4_h(x2, x2h, i); break;
        default: conv4_h(x0, x0h, i); break;
    }
}
__global__ void conv_w(const float* __restrict__ Wk, h16* __restrict__ wkh, h16* __restrict__ wkl,
                       const float* __restrict__ Wq, h16* __restrict__ wqh, h16* __restrict__ wql,
                       const float* __restrict__ Wv, h16* __restrict__ wvh,
                       const float* __restrict__ Wu, h16* __restrict__ wuh)
{
    const int i = blockIdx.x * 256 + threadIdx.x;
    switch (blockIdx.y) {
        case 0: split4_h(Wk, wkh, wkl, i); break;
        case 1: split4_h(Wq, wqh, wql, i); break;
        case 2: conv4_h(Wv, wvh, i); break;
        default: conv4_h(Wu, wuh, i); break;
    }
}

// ---------------- pool init + logits ----------------
__global__ void init_pool(float* __restrict__ psum, unsigned* __restrict__ pmax)
{
    const int i = blockIdx.x * 256 + threadIdx.x;
    if (i < BB * DD) { psum[i] = 0.f; pmax[i] = 0u; }
}

__global__ void logits_kernel(const float* __restrict__ psum,
                              const unsigned* __restrict__ pmax,
                              const float* __restrict__ Wm,
                              const float* __restrict__ bm,
                              float* __restrict__ out)
{
    const int b = blockIdx.x;
    __shared__ float ps[DD];
    __shared__ float red[4][OUTN];
    for (int i = threadIdx.x; i < DD; i += 256)
        ps[i] = psum[b * DD + i] * (1.f / LL) + fdec(pmax[b * DD + i]);
    __syncthreads();
    const int o = threadIdx.x & 63, part = threadIdx.x >> 6;
    float s = 0.f;
    const float* w = Wm + (long)o * DD + part * 256;
    const float* p = ps + part * 256;
    #pragma unroll 8
    for (int kk = 0; kk < 256; ++kk) s += p[kk] * w[kk];
    red[part][o] = s;
    __syncthreads();
    if (part == 0)
        out[b * OUTN + o] = red[0][o] + red[1][o] + red[2][o] + red[3][o] + bm[o];
}

// =================================================================
extern "C" void kernel_launch(void* const* d_in, const int* in_sizes, int n_in,
                              void* d_out, int out_size)
{
    const float* x0   = (const float*)d_in[0];
    const float* x1   = (const float*)d_in[1];
    const float* x2   = (const float*)d_in[2];
    const float* Wk   = (const float*)d_in[5];
    const float* Wq   = (const float*)d_in[6];
    const float* Wv   = (const float*)d_in[7];
    const float* Wu   = (const float*)d_in[8];
    const float* bu   = (const float*)d_in[9];
    const float* Wmlp = (const float*)d_in[10];
    const float* bmlp = (const float*)d_in[11];
    float* out = (float*)d_out;

    h16  *x1h,*x2h,*x0h,*wkh,*wkl,*wqh,*wql,*wvh,*wuh,*vv,*att;
    bf16 *qh,*ql,*kh,*kl;
    float *psum; unsigned *pmax;
    cudaGetSymbolAddress((void**)&x1h, g_x1h);
    cudaGetSymbolAddress((void**)&x2h, g_x2h);
    cudaGetSymbolAddress((void**)&x0h, g_x0h);
    cudaGetSymbolAddress((void**)&wkh, g_wkh); cudaGetSymbolAddress((void**)&wkl, g_wkl);
    cudaGetSymbolAddress((void**)&wqh, g_wqh); cudaGetSymbolAddress((void**)&wql, g_wql);
    cudaGetSymbolAddress((void**)&wvh, g_wvh);
    cudaGetSymbolAddress((void**)&wuh, g_wuh);
    cudaGetSymbolAddress((void**)&qh,  g_qh);  cudaGetSymbolAddress((void**)&ql,  g_ql);
    cudaGetSymbolAddress((void**)&kh,  g_kh);  cudaGetSymbolAddress((void**)&kl,  g_kl);
    cudaGetSymbolAddress((void**)&vv,  g_vv);  cudaGetSymbolAddress((void**)&att, g_att);
    cudaGetSymbolAddress((void**)&psum, g_psum);
    cudaGetSymbolAddress((void**)&pmax, g_pmax);

    const float scale = powf((float)KHD, -0.25f);
    const int M = BB * LL;

    constexpr int SM_QK = 4 * 3 * 128 * 24 * 2;   // 73728
    constexpr int SM_H1 = 4 * 2 * 128 * 24 * 2;   // 49152
    constexpr int SM_FL = 2*128*136*2 + 2*3*64*136*2;  // 174080
    cudaFuncSetAttribute(gemm_qk,    cudaFuncAttributeMaxDynamicSharedMemorySize, SM_QK);
    cudaFuncSetAttribute(gemm_h1<0>, cudaFuncAttributeMaxDynamicSharedMemorySize, SM_H1);
    cudaFuncSetAttribute(gemm_h1<1>, cudaFuncAttributeMaxDynamicSharedMemorySize, SM_H1);
    cudaFuncSetAttribute(flash_k,    cudaFuncAttributeMaxDynamicSharedMemorySize, SM_FL);

    // --- converts ---
    {
        dim3 gx(BB * LL * DD / 4 / 256, 3);
        conv_x<<<gx, 256>>>(x1, x1h, x2, x2h, x0, x0h);
        dim3 gw(DD * DD / 4 / 256, 4);
        conv_w<<<gw, 256>>>(Wk, wkh, wkl, Wq, wqh, wql, Wv, wvh, Wu, wuh);
    }
    init_pool<<<(BB * DD + 255) / 256, 256>>>(psum, pmax);

    dim3 blk(256);

    // --- q & k projections (fp16 2-MMA, z=2) + v ---
    {
        dim3 g2(DD / 128, M / 128, 2);
        gemm_qk<<<g2, blk, SM_QK>>>(x2h, wkh, wkl, qh, ql,
                                    x1h, wqh, wql, kh, kl, scale);
        dim3 g1(DD / 128, M / 128);
        gemm_h1<0><<<g1, blk, SM_H1>>>(x0h, wvh, vv, nullptr, nullptr, nullptr);
    }

    // --- fused attention ---
    {
        dim3 grid(LL / 128, BB * HH);
        flash_k<<<grid, blk, SM_FL>>>(qh, ql, kh, kl, vv, att);
    }

    // --- unify (1-MMA) + fused pooling ---
    {
        dim3 g1(DD / 128, M / 128);
        gemm_h1<1><<<g1, blk, SM_H1>>>(att, wuh, nullptr, bu, psum, pmax);
    }

    // --- logits ---
    logits_kernel<<<BB, 256>>>(psum, pmax, Wmlp, bmlp, out);
}

// round 13
// speedup vs baseline: 1.9480x; 1.4551x over previous
#include <cuda_runtime.h>
#include <cuda_fp16.h>
#include <math.h>
#include <stdint.h>

#define BB 16
#define LL 1024
#define DD 1024
#define HH 8
#define KHD 128
#define OUTN 64

typedef __half  h16;
typedef __half2 h162;

// ---------------- scratch ----------------
__device__ h16 g_x0h[BB*LL*DD];
__device__ h16 g_x1h[BB*LL*DD];
__device__ h16 g_x2h[BB*LL*DD];
__device__ h16 g_wk[DD*DD], g_wq[DD*DD], g_wv[DD*DD], g_wu[DD*DD];
__device__ h16 g_qq[BB*LL*DD], g_kk[BB*LL*DD], g_vv[BB*LL*DD];
__device__ h16 g_att[BB*LL*DD];
__device__ float    g_psum[BB*DD];
__device__ unsigned g_pmax[BB*DD];

// ---------------- helpers ----------------
__device__ __forceinline__ uint32_t pkh(h16 x, h16 y) {
    h162 t; t.x = x; t.y = y; return *(uint32_t*)&t;
}
__device__ __forceinline__ void cpa16(void* s, const void* g) {
    uint32_t sa = (uint32_t)__cvta_generic_to_shared(s);
    asm volatile("cp.async.cg.shared.global [%0], [%1], 16;" :: "r"(sa), "l"(g));
}
__device__ __forceinline__ void cp_commit() {
    asm volatile("cp.async.commit_group;" ::: "memory");
}
__device__ __forceinline__ void cp_wait1() {
    asm volatile("cp.async.wait_group 1;" ::: "memory");
}
__device__ __forceinline__ void cp_wait2() {
    asm volatile("cp.async.wait_group 2;" ::: "memory");
}
__device__ __forceinline__ void ldsm_x4(uint32_t* r, const void* p) {
    uint32_t a = (uint32_t)__cvta_generic_to_shared(p);
    asm volatile("ldmatrix.sync.aligned.m8n8.x4.shared.b16 {%0,%1,%2,%3}, [%4];"
        : "=r"(r[0]), "=r"(r[1]), "=r"(r[2]), "=r"(r[3]) : "r"(a));
}
__device__ __forceinline__ void ldsm_x4t(uint32_t* r, const void* p) {
    uint32_t a = (uint32_t)__cvta_generic_to_shared(p);
    asm volatile("ldmatrix.sync.aligned.m8n8.x4.trans.shared.b16 {%0,%1,%2,%3}, [%4];"
        : "=r"(r[0]), "=r"(r[1]), "=r"(r[2]), "=r"(r[3]) : "r"(a));
}
__device__ __forceinline__ void mma_f16(float* c, const uint32_t* a, const uint32_t* b) {
    asm volatile(
        "mma.sync.aligned.m16n8k16.row.col.f32.f16.f16.f32 "
        "{%0,%1,%2,%3},{%4,%5,%6,%7},{%8,%9},{%0,%1,%2,%3};"
        : "+f"(c[0]), "+f"(c[1]), "+f"(c[2]), "+f"(c[3])
        : "r"(a[0]), "r"(a[1]), "r"(a[2]), "r"(a[3]), "r"(b[0]), "r"(b[1]));
}
__device__ __forceinline__ unsigned fkey(float v) {
    unsigned u = __float_as_uint(v);
    return (u & 0x80000000u) ? ~u : (u | 0x80000000u);
}
__device__ __forceinline__ float fdec(unsigned k) {
    unsigned u = (k & 0x80000000u) ? (k ^ 0x80000000u) : ~k;
    return __uint_as_float(u);
}

// =================================================================
// Projections: fp16 1-MMA TN GEMM, z-batched over {q,k,v}.
// C = A @ B^T (fp16 out). BM=BN=128, BK=16, 4-stage, 2 CTA/SM.
// =================================================================
__global__ void __launch_bounds__(256, 2)
gemm_proj(const h16* __restrict__ A0, const h16* __restrict__ B0, h16* __restrict__ C0,
          const h16* __restrict__ A1, const h16* __restrict__ B1, h16* __restrict__ C1,
          const h16* __restrict__ A2, const h16* __restrict__ B2, h16* __restrict__ C2)
{
    extern __shared__ __align__(16) char smem[];
    constexpr int RS  = 24;
    constexpr int ARR = 128 * RS;
    constexpr int STG = 2 * ARR;

    const h16* Ax = (blockIdx.z == 0) ? A0 : (blockIdx.z == 1) ? A1 : A2;
    const h16* Bx = (blockIdx.z == 0) ? B0 : (blockIdx.z == 1) ? B1 : B2;
    h16*       Cx = (blockIdx.z == 0) ? C0 : (blockIdx.z == 1) ? C1 : C2;

    const int bm = blockIdx.y * 128, bn = blockIdx.x * 128;
    const int u = threadIdx.x, wid = u >> 5, lane = u & 31;
    const int wm = (wid >> 2) * 64, wn = (wid & 3) * 32;

    float acc[4][4][4];
    #pragma unroll
    for (int i = 0; i < 4; ++i)
        #pragma unroll
        for (int j = 0; j < 4; ++j)
            #pragma unroll
            for (int p = 0; p < 4; ++p) acc[i][j][p] = 0.f;

    const int srow = u >> 1, shalf = (u & 1) * 8;
    auto stage = [&](int buf, int k0) {
        h16* s0 = (h16*)smem + (long)buf * STG + srow * RS + shalf;
        cpa16(s0,       Ax + (long)(bm + srow) * DD + k0 + shalf);
        cpa16(s0 + ARR, Bx + (long)(bn + srow) * DD + k0 + shalf);
    };

    constexpr int nst = DD / 16;
    #pragma unroll
    for (int t = 0; t < 3; ++t) { stage(t, t * 16); cp_commit(); }

    const int arow = lane & 15, asel = (lane >> 4) * 8;
    const int brow = ((lane >> 4) & 1) * 8 + (lane & 7);
    const int bcol = ((lane >> 3) & 1) * 8;

    for (int s = 0; s < nst; ++s) {
        cp_wait2();
        __syncthreads();
        if (s + 3 < nst) stage((s + 3) & 3, (s + 3) * 16);
        cp_commit();

        const h16* base = (const h16*)smem + (long)(s & 3) * STG;
        const h16* sA = base;
        const h16* sB = base + ARR;

        uint32_t ah[4][4];
        #pragma unroll
        for (int mt = 0; mt < 4; ++mt)
            ldsm_x4(ah[mt], sA + (wm + mt * 16 + arow) * RS + asel);
        #pragma unroll
        for (int np = 0; np < 2; ++np) {
            uint32_t bh4[4];
            ldsm_x4(bh4, sB + (wn + np * 16 + brow) * RS + bcol);
            #pragma unroll
            for (int half = 0; half < 2; ++half) {
                const int nt = np * 2 + half;
                #pragma unroll
                for (int mt = 0; mt < 4; ++mt)
                    mma_f16(acc[mt][nt], ah[mt], bh4 + half * 2);
            }
        }
    }

    const int tr = lane >> 2, tc = lane & 3;
    #pragma unroll
    for (int mt = 0; mt < 4; ++mt) {
        const int row = bm + wm + mt * 16 + tr;
        #pragma unroll
        for (int nt = 0; nt < 4; ++nt) {
            const int col = bn + wn + nt * 8 + tc * 2;
            const float* c = acc[mt][nt];
            *(uint32_t*)&Cx[(long)row * DD + col] =
                pkh(__float2half_rn(c[0]), __float2half_rn(c[1]));
            *(uint32_t*)&Cx[(long)(row + 8) * DD + col] =
                pkh(__float2half_rn(c[2]), __float2half_rn(c[3]));
        }
    }
}

// =================================================================
// Unify GEMM: fp16 1-MMA TN + fused mean/max pooling epilogue.
// =================================================================
__global__ void __launch_bounds__(256, 2)
gemm_uni(const h16* __restrict__ Ax, const h16* __restrict__ Bx,
         const float* __restrict__ bias,
         float* __restrict__ psum, unsigned* __restrict__ pmax)
{
    extern __shared__ __align__(16) char smem[];
    constexpr int RS  = 24;
    constexpr int ARR = 128 * RS;
    constexpr int STG = 2 * ARR;

    const int bm = blockIdx.y * 128, bn = blockIdx.x * 128;
    const int u = threadIdx.x, wid = u >> 5, lane = u & 31;
    const int wm = (wid >> 2) * 64, wn = (wid & 3) * 32;

    float acc[4][4][4];
    #pragma unroll
    for (int i = 0; i < 4; ++i)
        #pragma unroll
        for (int j = 0; j < 4; ++j)
            #pragma unroll
            for (int p = 0; p < 4; ++p) acc[i][j][p] = 0.f;

    const int srow = u >> 1, shalf = (u & 1) * 8;
    auto stage = [&](int buf, int k0) {
        h16* s0 = (h16*)smem + (long)buf * STG + srow * RS + shalf;
        cpa16(s0,       Ax + (long)(bm + srow) * DD + k0 + shalf);
        cpa16(s0 + ARR, Bx + (long)(bn + srow) * DD + k0 + shalf);
    };

    constexpr int nst = DD / 16;
    #pragma unroll
    for (int t = 0; t < 3; ++t) { stage(t, t * 16); cp_commit(); }

    const int arow = lane & 15, asel = (lane >> 4) * 8;
    const int brow = ((lane >> 4) & 1) * 8 + (lane & 7);
    const int bcol = ((lane >> 3) & 1) * 8;

    for (int s = 0; s < nst; ++s) {
        cp_wait2();
        __syncthreads();
        if (s + 3 < nst) stage((s + 3) & 3, (s + 3) * 16);
        cp_commit();

        const h16* base = (const h16*)smem + (long)(s & 3) * STG;
        const h16* sA = base;
        const h16* sB = base + ARR;

        uint32_t ah[4][4];
        #pragma unroll
        for (int mt = 0; mt < 4; ++mt)
            ldsm_x4(ah[mt], sA + (wm + mt * 16 + arow) * RS + asel);
        #pragma unroll
        for (int np = 0; np < 2; ++np) {
            uint32_t bh4[4];
            ldsm_x4(bh4, sB + (wn + np * 16 + brow) * RS + bcol);
            #pragma unroll
            for (int half = 0; half < 2; ++half) {
                const int nt = np * 2 + half;
                #pragma unroll
                for (int mt = 0; mt < 4; ++mt)
                    mma_f16(acc[mt][nt], ah[mt], bh4 + half * 2);
            }
        }
    }

    const int tr = lane >> 2, tc = lane & 3;
    const int b = bm >> 10;
    float sum[4][2], mx[4][2];
    #pragma unroll
    for (int nt = 0; nt < 4; ++nt) {
        #pragma unroll
        for (int j = 0; j < 2; ++j) {
            const int col = bn + wn + nt * 8 + tc * 2 + j;
            const float bv = __ldg(bias + col);
            float s_ = 0.f, m_ = -1e30f;
            #pragma unroll
            for (int mt = 0; mt < 4; ++mt) {
                const float v0 = acc[mt][nt][j] + bv;
                const float v1 = acc[mt][nt][j + 2] + bv;
                s_ += v0 + v1;
                m_ = fmaxf(m_, fmaxf(v0, v1));
            }
            sum[nt][j] = s_; mx[nt][j] = m_;
        }
    }
    #pragma unroll
    for (int o = 4; o <= 16; o <<= 1) {
        #pragma unroll
        for (int nt = 0; nt < 4; ++nt)
            #pragma unroll
            for (int j = 0; j < 2; ++j) {
                sum[nt][j] += __shfl_xor_sync(~0u, sum[nt][j], o);
                mx[nt][j] = fmaxf(mx[nt][j], __shfl_xor_sync(~0u, mx[nt][j], o));
            }
    }
    if (tr == 0) {
        #pragma unroll
        for (int nt = 0; nt < 4; ++nt)
            #pragma unroll
            for (int j = 0; j < 2; ++j) {
                const int col = bn + wn + nt * 8 + tc * 2 + j;
                atomicAdd(&psum[b * DD + col], sum[nt][j]);
                atomicMax(&pmax[b * DD + col], fkey(mx[nt][j]));
            }
    }
}

// =================================================================
// Fused flash attention — full fp16: QK^T 1-MMA, PV 1-MMA.
// Attention scale^2 folded into exp arguments. 2 CTA/SM target.
// =================================================================
__global__ void __launch_bounds__(256, 2)
flash_k(const h16* __restrict__ Q, const h16* __restrict__ K,
        const h16* __restrict__ V, h16* __restrict__ O_)
{
    extern __shared__ __align__(16) char sm[];
    constexpr int QS = 128 * 136;   // elems
    constexpr int TS = 64 * 136;    // elems per array per stage
    h16* sQ = (h16*)sm;
    h16* sT = sQ + QS;              // [2 stages][K,V][TS]
    constexpr float SC2 = 0.08838834764831845f;   // 1/sqrt(128)

    const int bh = blockIdx.y, b = bh >> 3, h = bh & 7;
    const int q0 = blockIdx.x * 128;
    const int u = threadIdx.x, wid = u >> 5, lane = u & 31;
    const int tr = lane >> 2, tc = lane & 3;

    const long qg = ((long)b * LL + q0) * DD + h * KHD;
    const long kg = (long)b * LL * DD + h * KHD;

    for (int c = u; c < 2048; c += 256) {
        const int r = c >> 4, s = (c & 15) * 8;
        cpa16(sQ + r * 136 + s, Q + qg + (long)r * DD + s);
    }
    auto stage = [&](int buf, int kv0) {
        h16* pK = sT + buf * 2 * TS;
        h16* pV = pK + TS;
        for (int c = u; c < 1024; c += 256) {
            const int r = c >> 4, s = (c & 15) * 8;
            const long g = kg + (long)(kv0 + r) * DD + s;
            cpa16(pK + r * 136 + s, K + g);
            cpa16(pV + r * 136 + s, V + g);
        }
    };
    stage(0, 0);
    cp_commit();

    float O[16][4];
    #pragma unroll
    for (int i = 0; i < 16; ++i)
        #pragma unroll
        for (int j = 0; j < 4; ++j) O[i][j] = 0.f;
    float m0 = -1e30f, m1 = -1e30f, l0 = 0.f, l1 = 0.f;

    const int brow = ((lane >> 4) & 1) * 8 + (lane & 7);
    const int bcol = ((lane >> 3) & 1) * 8;
    const int vrow = ((lane >> 3) & 1) * 8 + (lane & 7);
    const int vsel = (lane >> 4);

    for (int t = 0; t < 16; ++t) {
        if (t + 1 < 16) stage((t + 1) & 1, (t + 1) * 64);
        cp_commit();
        cp_wait1();
        __syncthreads();

        const h16* cK = sT + (t & 1) * 2 * TS;
        const h16* cV = cK + TS;

        // ---- S = Q K^T (fp16 1-MMA, raw scores; scale folded later) ----
        float S[8][4];
        #pragma unroll
        for (int i = 0; i < 8; ++i)
            #pragma unroll
            for (int j = 0; j < 4; ++j) S[i][j] = 0.f;

        #pragma unroll
        for (int kk = 0; kk < 128; kk += 16) {
            uint32_t ah[4];
            const int aoff = (wid * 16 + (lane & 15)) * 136 + kk + (lane >> 4) * 8;
            ldsm_x4(ah, sQ + aoff);
            #pragma unroll
            for (int np = 0; np < 4; ++np) {
                uint32_t bh4[4];
                const int boff = (np * 16 + brow) * 136 + kk + bcol;
                ldsm_x4(bh4, cK + boff);
                mma_f16(S[np * 2],     ah, bh4);
                mma_f16(S[np * 2 + 1], ah, bh4 + 2);
            }
        }

        // ---- online softmax (exp arg scaled by SC2) ----
        float rm0 = -1e30f, rm1 = -1e30f;
        #pragma unroll
        for (int nt = 0; nt < 8; ++nt) {
            rm0 = fmaxf(rm0, fmaxf(S[nt][0], S[nt][1]));
            rm1 = fmaxf(rm1, fmaxf(S[nt][2], S[nt][3]));
        }
        rm0 = fmaxf(rm0, __shfl_xor_sync(~0u, rm0, 1));
        rm0 = fmaxf(rm0, __shfl_xor_sync(~0u, rm0, 2));
        rm1 = fmaxf(rm1, __shfl_xor_sync(~0u, rm1, 1));
        rm1 = fmaxf(rm1, __shfl_xor_sync(~0u, rm1, 2));
        const float M0 = fmaxf(m0, rm0), M1 = fmaxf(m1, rm1);
        const float f0 = __expf((m0 - M0) * SC2), f1 = __expf((m1 - M1) * SC2);
        m0 = M0; m1 = M1;
        l0 *= f0; l1 *= f1;
        #pragma unroll
        for (int dt = 0; dt < 16; ++dt) {
            O[dt][0] *= f0; O[dt][1] *= f0;
            O[dt][2] *= f1; O[dt][3] *= f1;
        }

        // ---- P = exp(SC2*(S-M)) fp16; PV 1-MMA ----
        #pragma unroll
        for (int kc = 0; kc < 4; ++kc) {
            uint32_t pa[4];
            #pragma unroll
            for (int half = 0; half < 2; ++half) {
                const int nt = kc * 2 + half;
                const float p0 = __expf((S[nt][0] - M0) * SC2);
                const float p1 = __expf((S[nt][1] - M0) * SC2);
                const float p2 = __expf((S[nt][2] - M1) * SC2);
                const float p3 = __expf((S[nt][3] - M1) * SC2);
                l0 += p0 + p1; l1 += p2 + p3;
                pa[half ? 2 : 0] = pkh(__float2half_rn(p0), __float2half_rn(p1));
                pa[half ? 3 : 1] = pkh(__float2half_rn(p2), __float2half_rn(p3));
            }
            #pragma unroll
            for (int dt = 0; dt < 16; dt += 2) {
                uint32_t bv[4];
                const int voff = (kc * 16 + vrow) * 136 + (dt + vsel) * 8;
                ldsm_x4t(bv, cV + voff);
                mma_f16(O[dt],     pa, bv);
                mma_f16(O[dt + 1], pa, bv + 2);
            }
        }
        __syncthreads();
    }

    l0 += __shfl_xor_sync(~0u, l0, 1); l0 += __shfl_xor_sync(~0u, l0, 2);
    l1 += __shfl_xor_sync(~0u, l1, 1); l1 += __shfl_xor_sync(~0u, l1, 2);
    const float i0 = 1.f / l0, i1 = 1.f / l1;
    const long og = ((long)b * LL + q0 + wid * 16) * DD + h * KHD;
    #pragma unroll
    for (int dt = 0; dt < 16; ++dt) {
        const int col = dt * 8 + tc * 2;
        *(uint32_t*)&O_[og + (long)tr * DD + col] =
            pkh(__float2half_rn(O[dt][0] * i0), __float2half_rn(O[dt][1] * i0));
        *(uint32_t*)&O_[og + (long)(tr + 8) * DD + col] =
            pkh(__float2half_rn(O[dt][2] * i1), __float2half_rn(O[dt][3] * i1));
    }
}

// ---------------- converts ----------------
__device__ __forceinline__ void conv4_h(const float* in, h16* hi, int i)
{
    const float4 v = ((const float4*)in)[i];
    ((uint32_t*)hi)[i * 2]     = pkh(__float2half_rn(v.x), __float2half_rn(v.y));
    ((uint32_t*)hi)[i * 2 + 1] = pkh(__float2half_rn(v.z), __float2half_rn(v.w));
}

__global__ void conv_x(const float* __restrict__ x1, h16* __restrict__ x1h,
                       const float* __restrict__ x2, h16* __restrict__ x2h,
                       const float* __restrict__ x0, h16* __restrict__ x0h)
{
    const int i = blockIdx.x * 256 + threadIdx.x;
    switch (blockIdx.y) {
        case 0: conv4_h(x1, x1h, i); break;
        case 1: conv4_h(x2, x2h, i); break;
        default: conv4_h(x0, x0h, i); break;
    }
}
__global__ void conv_w(const float* __restrict__ Wk, h16* __restrict__ wk,
                       const float* __restrict__ Wq, h16* __restrict__ wq,
                       const float* __restrict__ Wv, h16* __restrict__ wv,
                       const float* __restrict__ Wu, h16* __restrict__ wu)
{
    const int i = blockIdx.x * 256 + threadIdx.x;
    switch (blockIdx.y) {
        case 0: conv4_h(Wk, wk, i); break;
        case 1: conv4_h(Wq, wq, i); break;
        case 2: conv4_h(Wv, wv, i); break;
        default: conv4_h(Wu, wu, i); break;
    }
}

// ---------------- pool init + logits ----------------
__global__ void init_pool(float* __restrict__ psum, unsigned* __restrict__ pmax)
{
    const int i = blockIdx.x * 256 + threadIdx.x;
    if (i < BB * DD) { psum[i] = 0.f; pmax[i] = 0u; }
}

__global__ void logits_kernel(const float* __restrict__ psum,
                              const unsigned* __restrict__ pmax,
                              const float* __restrict__ Wm,
                              const float* __restrict__ bm,
                              float* __restrict__ out)
{
    const int b = blockIdx.x;
    __shared__ float ps[DD];
    __shared__ float red[4][OUTN];
    for (int i = threadIdx.x; i < DD; i += 256)
        ps[i] = psum[b * DD + i] * (1.f / LL) + fdec(pmax[b * DD + i]);
    __syncthreads();
    const int o = threadIdx.x & 63, part = threadIdx.x >> 6;
    float s = 0.f;
    const float* w = Wm + (long)o * DD + part * 256;
    const float* p = ps + part * 256;
    #pragma unroll 8
    for (int kk = 0; kk < 256; ++kk) s += p[kk] * w[kk];
    red[part][o] = s;
    __syncthreads();
    if (part == 0)
        out[b * OUTN + o] = red[0][o] + red[1][o] + red[2][o] + red[3][o] + bm[o];
}

// =================================================================
extern "C" void kernel_launch(void* const* d_in, const int* in_sizes, int n_in,
                              void* d_out, int out_size)
{
    const float* x0   = (const float*)d_in[0];
    const float* x1   = (const float*)d_in[1];
    const float* x2   = (const float*)d_in[2];
    const float* Wk   = (const float*)d_in[5];
    const float* Wq   = (const float*)d_in[6];
    const float* Wv   = (const float*)d_in[7];
    const float* Wu   = (const float*)d_in[8];
    const float* bu   = (const float*)d_in[9];
    const float* Wmlp = (const float*)d_in[10];
    const float* bmlp = (const float*)d_in[11];
    float* out = (float*)d_out;

    h16 *x0h,*x1h,*x2h,*wk,*wq,*wv,*wu,*qq,*kk,*vv,*att;
    float *psum; unsigned *pmax;
    cudaGetSymbolAddress((void**)&x0h, g_x0h);
    cudaGetSymbolAddress((void**)&x1h, g_x1h);
    cudaGetSymbolAddress((void**)&x2h, g_x2h);
    cudaGetSymbolAddress((void**)&wk,  g_wk);
    cudaGetSymbolAddress((void**)&wq,  g_wq);
    cudaGetSymbolAddress((void**)&wv,  g_wv);
    cudaGetSymbolAddress((void**)&wu,  g_wu);
    cudaGetSymbolAddress((void**)&qq,  g_qq);
    cudaGetSymbolAddress((void**)&kk,  g_kk);
    cudaGetSymbolAddress((void**)&vv,  g_vv);
    cudaGetSymbolAddress((void**)&att, g_att);
    cudaGetSymbolAddress((void**)&psum, g_psum);
    cudaGetSymbolAddress((void**)&pmax, g_pmax);

    const int M = BB * LL;

    constexpr int SM_PRJ = 4 * 2 * 128 * 24 * 2;               // 49152
    constexpr int SM_FL  = (128 * 136 + 2 * 2 * 64 * 136) * 2; // 104448
    cudaFuncSetAttribute(gemm_proj, cudaFuncAttributeMaxDynamicSharedMemorySize, SM_PRJ);
    cudaFuncSetAttribute(gemm_uni,  cudaFuncAttributeMaxDynamicSharedMemorySize, SM_PRJ);
    cudaFuncSetAttribute(flash_k,   cudaFuncAttributeMaxDynamicSharedMemorySize, SM_FL);

    // --- converts + pool init ---
    {
        dim3 gx(BB * LL * DD / 4 / 256, 3);
        conv_x<<<gx, 256>>>(x1, x1h, x2, x2h, x0, x0h);
        dim3 gw(DD * DD / 4 / 256, 4);
        conv_w<<<gw, 256>>>(Wk, wk, Wq, wq, Wv, wv, Wu, wu);
    }
    init_pool<<<(BB * DD + 255) / 256, 256>>>(psum, pmax);

    dim3 blk(256);

    // --- q, k, v projections (one z=3 launch; scale folded into flash) ---
    // q = x2 @ Wk^T,  k = x1 @ Wq^T,  v = x0 @ Wv^T  (reference weight swap)
    {
        dim3 g3(DD / 128, M / 128, 3);
        gemm_proj<<<g3, blk, SM_PRJ>>>(x2h, wk, qq,
                                       x1h, wq, kk,
                                       x0h, wv, vv);
    }

    // --- fused attention ---
    {
        dim3 grid(LL / 128, BB * HH);
        flash_k<<<grid, blk, SM_FL>>>(qq, kk, vv, att);
    }

    // --- unify + fused pooling ---
    {
        dim3 g1(DD / 128, M / 128);
        gemm_uni<<<g1, blk, SM_PRJ>>>(att, wu, bu, psum, pmax);
    }

    // --- logits ---
    logits_kernel<<<BB, 256>>>(psum, pmax, Wmlp, bmlp, out);
}